// round 1
// baseline (speedup 1.0000x reference)
#include <cuda_runtime.h>
#include <math.h>

// Closed-form reduction of the 4-qubit circuit:
//   z = cosB * cos(t1)cos(t2)cos(t3) - sinB*cos(phi0)*cos(phi1) * sin(t0)sin(t1)
//   t_i = tanh(W1[i]·x + b1[i]) + qw[0,i]
// Derivation: RY layers fuse (product state); Heisenberg back-prop of
// cosB*Z0 - sinB*X0 through CNOT chain gives Z1Z2Z3 and X0X1.

__device__ __align__(16) float g_params[48];

__global__ void setup_kernel(const float* __restrict__ W1,
                             const float* __restrict__ b1,
                             const float* __restrict__ qw,
                             const float* __restrict__ W2,
                             const float* __restrict__ b2,
                             const float* __restrict__ W3,
                             const float* __restrict__ b3) {
    const float S = 2.0f * 1.4426950408889634f;  // 2*log2(e) for exp2-based tanh
    #pragma unroll
    for (int i = 0; i < 4; i++) {
        #pragma unroll
        for (int j = 0; j < 4; j++)
            g_params[i * 4 + j] = S * W1[i * 4 + j];
    }
    #pragma unroll
    for (int i = 0; i < 4; i++) g_params[16 + i] = S * b1[i];
    #pragma unroll
    for (int i = 0; i < 4; i++) g_params[20 + i] = qw[i];  // qw[0,i] angle offsets
    float beta = qw[8];                                     // qw[2,0]
    g_params[24] = cosf(beta);
    g_params[25] = sinf(beta) * cosf(qw[4]) * cosf(qw[5]);  // phi0=qw[1,0], phi1=qw[1,1]
    g_params[26] = 0.0f;
    g_params[27] = 0.0f;
    #pragma unroll
    for (int i = 0; i < 4; i++) g_params[28 + i] = W2[i];
    #pragma unroll
    for (int i = 0; i < 4; i++) g_params[32 + i] = b2[i];
    #pragma unroll
    for (int i = 0; i < 8; i++) g_params[36 + i] = W3[i];
    g_params[44] = b3[0];
    g_params[45] = b3[1];
    g_params[46] = 0.0f;
    g_params[47] = 0.0f;
}

// tanh(p) where q = 2*log2(e)*p is pre-scaled: tanh = 1 - 2/(exp2(q)+1).
// Graceful saturation at +-1 for |q| large (inf -> rcp -> 0).
__device__ __forceinline__ float tanh_from_scaled(float q) {
    float e;
    asm("ex2.approx.f32 %0, %1;" : "=f"(e) : "f"(q));
    float d = e + 1.0f;
    float r;
    asm("rcp.approx.f32 %0, %1;" : "=f"(r) : "f"(d));
    return fmaf(-2.0f, r, 1.0f);
}

__global__ __launch_bounds__(256) void qnn_kernel(const float4* __restrict__ x,
                                                  float2* __restrict__ out,
                                                  int n) {
    int i = blockIdx.x * blockDim.x + threadIdx.x;
    if (i >= n) return;

    const float4* __restrict__ P = reinterpret_cast<const float4*>(g_params);
    float4 w0 = P[0], w1 = P[1], w2 = P[2], w3 = P[3];
    float4 bb = P[4];   // scaled b1
    float4 off = P[5];  // qw[0,*]
    float4 cc = P[6];   // C1, C2
    float4 W2v = P[7], b2v = P[8], W3a = P[9], W3b = P[10], b3v = P[11];

    float4 xv = x[i];

    // pre-layer (rows 0..3 of W1 only; rows 4..7 unused downstream), pre-scaled by 2*log2e
    float q0 = fmaf(w0.x, xv.x, fmaf(w0.y, xv.y, fmaf(w0.z, xv.z, fmaf(w0.w, xv.w, bb.x))));
    float q1 = fmaf(w1.x, xv.x, fmaf(w1.y, xv.y, fmaf(w1.z, xv.z, fmaf(w1.w, xv.w, bb.y))));
    float q2 = fmaf(w2.x, xv.x, fmaf(w2.y, xv.y, fmaf(w2.z, xv.z, fmaf(w2.w, xv.w, bb.z))));
    float q3 = fmaf(w3.x, xv.x, fmaf(w3.y, xv.y, fmaf(w3.z, xv.z, fmaf(w3.w, xv.w, bb.w))));

    float t0 = tanh_from_scaled(q0) + off.x;
    float t1 = tanh_from_scaled(q1) + off.y;
    float t2 = tanh_from_scaled(q2) + off.z;
    float t3 = tanh_from_scaled(q3) + off.w;

    float st0 = __sinf(t0);
    float st1 = __sinf(t1);
    float ct1 = __cosf(t1);
    float ct2 = __cosf(t2);
    float ct3 = __cosf(t3);

    float z = cc.x * (ct1 * ct2 * ct3) - cc.y * (st0 * st1);

    // post-layer: relu(z*W2 + b2) @ W3^T + b3
    float g0 = fmaxf(fmaf(W2v.x, z, b2v.x), 0.0f);
    float g1 = fmaxf(fmaf(W2v.y, z, b2v.y), 0.0f);
    float g2 = fmaxf(fmaf(W2v.z, z, b2v.z), 0.0f);
    float g3 = fmaxf(fmaf(W2v.w, z, b2v.w), 0.0f);

    float o0 = fmaf(W3a.x, g0, fmaf(W3a.y, g1, fmaf(W3a.z, g2, fmaf(W3a.w, g3, b3v.x))));
    float o1 = fmaf(W3b.x, g0, fmaf(W3b.y, g1, fmaf(W3b.z, g2, fmaf(W3b.w, g3, b3v.y))));

    out[i] = make_float2(o0, o1);
}

extern "C" void kernel_launch(void* const* d_in, const int* in_sizes, int n_in,
                              void* d_out, int out_size) {
    const float* x  = (const float*)d_in[0];
    const float* W1 = (const float*)d_in[1];
    const float* b1 = (const float*)d_in[2];
    const float* qw = (const float*)d_in[3];
    const float* W2 = (const float*)d_in[4];
    const float* b2 = (const float*)d_in[5];
    const float* W3 = (const float*)d_in[6];
    const float* b3 = (const float*)d_in[7];

    int n = in_sizes[0] / 4;  // batch size

    setup_kernel<<<1, 1>>>(W1, b1, qw, W2, b2, W3, b3);

    int threads = 256;
    int blocks = (n + threads - 1) / threads;
    qnn_kernel<<<blocks, threads>>>(reinterpret_cast<const float4*>(x),
                                    reinterpret_cast<float2*>(d_out), n);
}

// round 2
// speedup vs baseline: 1.1532x; 1.1532x over previous
#include <cuda_runtime.h>
#include <math.h>

// Closed-form reduction of the 4-qubit circuit:
//   z = cosB * cos(t1)cos(t2)cos(t3) - sinB*cos(phi0)*cos(phi1) * sin(t0)sin(t1)
//   t_i = tanh(W1[i]*x + b1[i]) + qw[0,i]
// Single fused kernel: per-block cooperative param setup in SMEM (no second
// launch node), 2 samples per thread (float4-in x2, float4-out).

__device__ __forceinline__ float tanh_from_scaled(float q) {
    // tanh(p) where q = 2*log2(e)*p pre-scaled: tanh = 1 - 2/(exp2(q)+1)
    float e;
    asm("ex2.approx.f32 %0, %1;" : "=f"(e) : "f"(q));
    float d = e + 1.0f;
    float r;
    asm("rcp.approx.f32 %0, %1;" : "=f"(r) : "f"(d));
    return fmaf(-2.0f, r, 1.0f);
}

struct P4 { float4 w0, w1, w2, w3, bb, off, cc, W2v, b2v, W3a, W3b, b3v; };

__device__ __forceinline__ float2 sample_eval(const P4& p, float4 xv) {
    float q0 = fmaf(p.w0.x, xv.x, fmaf(p.w0.y, xv.y, fmaf(p.w0.z, xv.z, fmaf(p.w0.w, xv.w, p.bb.x))));
    float q1 = fmaf(p.w1.x, xv.x, fmaf(p.w1.y, xv.y, fmaf(p.w1.z, xv.z, fmaf(p.w1.w, xv.w, p.bb.y))));
    float q2 = fmaf(p.w2.x, xv.x, fmaf(p.w2.y, xv.y, fmaf(p.w2.z, xv.z, fmaf(p.w2.w, xv.w, p.bb.z))));
    float q3 = fmaf(p.w3.x, xv.x, fmaf(p.w3.y, xv.y, fmaf(p.w3.z, xv.z, fmaf(p.w3.w, xv.w, p.bb.w))));

    float t0 = tanh_from_scaled(q0) + p.off.x;
    float t1 = tanh_from_scaled(q1) + p.off.y;
    float t2 = tanh_from_scaled(q2) + p.off.z;
    float t3 = tanh_from_scaled(q3) + p.off.w;

    float st0 = __sinf(t0);
    float st1 = __sinf(t1);
    float ct1 = __cosf(t1);
    float ct2 = __cosf(t2);
    float ct3 = __cosf(t3);

    float z = p.cc.x * (ct1 * ct2 * ct3) - p.cc.y * (st0 * st1);

    float g0 = fmaxf(fmaf(p.W2v.x, z, p.b2v.x), 0.0f);
    float g1 = fmaxf(fmaf(p.W2v.y, z, p.b2v.y), 0.0f);
    float g2 = fmaxf(fmaf(p.W2v.z, z, p.b2v.z), 0.0f);
    float g3 = fmaxf(fmaf(p.W2v.w, z, p.b2v.w), 0.0f);

    float o0 = fmaf(p.W3a.x, g0, fmaf(p.W3a.y, g1, fmaf(p.W3a.z, g2, fmaf(p.W3a.w, g3, p.b3v.x))));
    float o1 = fmaf(p.W3b.x, g0, fmaf(p.W3b.y, g1, fmaf(p.W3b.z, g2, fmaf(p.W3b.w, g3, p.b3v.y))));
    return make_float2(o0, o1);
}

__global__ __launch_bounds__(256) void qnn_fused(
    const float4* __restrict__ x, float4* __restrict__ out,
    const float* __restrict__ W1, const float* __restrict__ b1,
    const float* __restrict__ qw, const float* __restrict__ W2,
    const float* __restrict__ b2, const float* __restrict__ W3,
    const float* __restrict__ b3, int npair)
{
    __shared__ __align__(16) float sp[48];

    int i = blockIdx.x * blockDim.x + threadIdx.x;
    bool active = (i < npair);

    // Issue payload loads before the barrier (independent of sp[])
    float4 xa = make_float4(0, 0, 0, 0), xb = xa;
    if (active) {
        xa = x[2 * i];
        xb = x[2 * i + 1];
    }

    // Cooperative per-block param setup (weights hit L2 after first blocks)
    const float S = 2.0f * 1.4426950408889634f;  // 2*log2(e)
    int t = threadIdx.x;
    if (t < 16)      sp[t] = S * W1[t];            // rows 0..3 of W1, pre-scaled
    else if (t < 20) sp[t] = S * b1[t - 16];
    else if (t < 24) sp[t] = qw[t - 20];           // qw[0,*]
    else if (t == 24) sp[24] = cosf(qw[8]);        // cos(beta), beta = qw[2,0]
    else if (t == 25) sp[25] = sinf(qw[8]) * cosf(qw[4]) * cosf(qw[5]);
    else if (t < 28)  sp[t] = 0.0f;
    else if (t < 32) sp[t] = W2[t - 28];
    else if (t < 36) sp[t] = b2[t - 32];
    else if (t < 44) sp[t] = W3[t - 36];
    else if (t < 46) sp[t] = b3[t - 44];
    else if (t < 48) sp[t] = 0.0f;
    __syncthreads();

    if (!active) return;

    const float4* sp4 = reinterpret_cast<const float4*>(sp);
    P4 p;
    p.w0 = sp4[0]; p.w1 = sp4[1]; p.w2 = sp4[2]; p.w3 = sp4[3];
    p.bb = sp4[4]; p.off = sp4[5]; p.cc = sp4[6];
    p.W2v = sp4[7]; p.b2v = sp4[8]; p.W3a = sp4[9]; p.W3b = sp4[10]; p.b3v = sp4[11];

    float2 ra = sample_eval(p, xa);
    float2 rb = sample_eval(p, xb);

    out[i] = make_float4(ra.x, ra.y, rb.x, rb.y);
}

extern "C" void kernel_launch(void* const* d_in, const int* in_sizes, int n_in,
                              void* d_out, int out_size) {
    const float* x  = (const float*)d_in[0];
    const float* W1 = (const float*)d_in[1];
    const float* b1 = (const float*)d_in[2];
    const float* qw = (const float*)d_in[3];
    const float* W2 = (const float*)d_in[4];
    const float* b2 = (const float*)d_in[5];
    const float* W3 = (const float*)d_in[6];
    const float* b3 = (const float*)d_in[7];

    int n = in_sizes[0] / 4;   // batch size (1048576, even)
    int npair = n / 2;

    int threads = 256;
    int blocks = (npair + threads - 1) / threads;
    qnn_fused<<<blocks, threads>>>(reinterpret_cast<const float4*>(x),
                                   reinterpret_cast<float4*>(d_out),
                                   W1, b1, qw, W2, b2, W3, b3, npair);
}